// round 17
// baseline (speedup 1.0000x reference)
#include <cuda_runtime.h>
#include <math.h>
#include <stdint.h>

#define TT   512
#define BB   64
#define II   1024
#define HH   1024
#define G4   4096      // 4*H
#define GRID 128       // persistent CTAs for recurrence

typedef unsigned long long ull;

// Static device scratch (no runtime alloc)
__device__ float g_xg[(size_t)TT * BB * G4];     // x_gates [T, B, 4H]
__device__ float g_a[(size_t)TT * BB * II];      // tf32-rounded input  [32768, 1024]
__device__ float g_b[(size_t)G4 * II];           // tf32-rounded w_ih   [4096, 1024]
__device__ float g_hr[2][BB * HH];               // rna-rounded h ping-pong [b][h]
__device__ unsigned g_bar;

__device__ __forceinline__ void cp16(uint32_t dst_smem, const void* src) {
    asm volatile("cp.async.cg.shared.global [%0], [%1], 16;"
                 :: "r"(dst_smem), "l"(src));
}
__device__ __forceinline__ uint32_t rna_tf32(float x) {
    uint32_t r; asm("cvt.rna.tf32.f32 %0, %1;" : "=r"(r) : "f"(x)); return r;
}
__device__ __forceinline__ void mma_tf32(float* c, const uint32_t* a,
                                         const uint32_t* b) {
    asm("mma.sync.aligned.m16n8k8.row.col.f32.tf32.tf32.f32 "
        "{%0,%1,%2,%3}, {%4,%5,%6,%7}, {%8,%9}, {%0,%1,%2,%3};"
        : "+f"(c[0]), "+f"(c[1]), "+f"(c[2]), "+f"(c[3])
        : "r"(a[0]), "r"(a[1]), "r"(a[2]), "r"(a[3]), "r"(b[0]), "r"(b[1]));
}
// fast tanh / sigmoid (|err| ~1e-6, clamped safe)
__device__ __forceinline__ float ftanh(float x) {
    const float xc = fminf(fmaxf(x, -15.0f), 15.0f);
    const float e = __expf(2.0f * xc);
    return __fdividef(e - 1.0f, e + 1.0f);
}
__device__ __forceinline__ float fsigm(float x) {
    const float e = __expf(-fmaxf(x, -80.0f));
    return __fdividef(1.0f, 1.0f + e);
}

// ---------------------------------------------------------------------------
// cvt pass: round input + w_ih to tf32 (rna) into g_a / g_b.
// ---------------------------------------------------------------------------
#define A_F4 8388608   // input float4 count
#define T_F4 9437184   // total float4 count
__global__ __launch_bounds__(256)
void cvt_tf32(const float* __restrict__ in, const float* __restrict__ wih)
{
    const int idx = blockIdx.x * 256 + threadIdx.x;
    const float4* src; float* dst; int i4;
    if (idx < A_F4) { src = (const float4*)in;  dst = g_a; i4 = idx; }
    else            { src = (const float4*)wih; dst = g_b; i4 = idx - A_F4; }
    float4 v = src[i4];
    uint4 o;
    o.x = rna_tf32(v.x); o.y = rna_tf32(v.y);
    o.z = rna_tf32(v.z); o.w = rna_tf32(v.w);
    *(uint4*)(dst + (size_t)i4 * 4) = o;
}

// ---------------------------------------------------------------------------
// Phase 1: tf32 mma.sync GEMM (proven R10..R15).
// ---------------------------------------------------------------------------
#define ATILE 4608
#define GEMM_SMEM (4 * ATILE * 4)

__device__ __forceinline__ void stage_ab(uint32_t sb, int s, const float* ga,
                                         const float* gb_, int kb, int tid)
{
    const uint32_t ab = sb + (uint32_t)(s * ATILE) * 4;
    const uint32_t bbse = sb + (uint32_t)((2 + s) * ATILE) * 4;
    #pragma unroll
    for (int r = 0; r < 4; r++) {
        const int id = tid + r * 256;
        const int row = id >> 3, k = (id & 7) * 4;
        cp16(ab + (uint32_t)(row * 36 + k) * 4,
             ga + (size_t)row * II + kb * 32 + k);
    }
    #pragma unroll
    for (int r = 0; r < 4; r++) {
        const int id = tid + r * 256;
        const int row = id >> 3, k = (id & 7) * 4;
        cp16(bbse + (uint32_t)(row * 36 + k) * 4,
             gb_ + (size_t)row * II + kb * 32 + k);
    }
    asm volatile("cp.async.commit_group;");
}

__global__ __launch_bounds__(256, 2)
void gemm_mma(const float* __restrict__ bih, const float* __restrict__ bhh,
              float* __restrict__ C)
{
    extern __shared__ float sm[];
    const uint32_t sbase = (uint32_t)__cvta_generic_to_shared(sm);

    const int tid = threadIdx.x;
    const int wid = tid >> 5, lid = tid & 31;
    const int wm = wid >> 2, wn = wid & 3;
    const int r = lid >> 2, cq = lid & 3;
    const int n0 = blockIdx.x * 128;
    const int m0 = blockIdx.y * 128;
    const float* ga  = g_a + (size_t)m0 * II;
    const float* gb_ = g_b + (size_t)n0 * II;

    float acc[4][4][4];
    #pragma unroll
    for (int i = 0; i < 4; i++)
        #pragma unroll
        for (int j = 0; j < 4; j++)
            #pragma unroll
            for (int q = 0; q < 4; q++) acc[i][j][q] = 0.0f;

    stage_ab(sbase, 0, ga, gb_, 0, tid);

    for (int kb = 0; kb < 32; kb++) {
        if (kb < 31) {
            stage_ab(sbase, (kb + 1) & 1, ga, gb_, kb + 1, tid);
            asm volatile("cp.async.wait_group 1;");
        } else {
            asm volatile("cp.async.wait_group 0;");
        }
        __syncthreads();

        const uint32_t* Au = (const uint32_t*)(sm + (kb & 1) * ATILE);
        const uint32_t* Bu = (const uint32_t*)(sm + (2 + (kb & 1)) * ATILE);

        #pragma unroll
        for (int ks = 0; ks < 4; ks++) {
            const int k0 = ks * 8;
            uint32_t a[4][4], b[4][2];
            #pragma unroll
            for (int i = 0; i < 4; i++) {
                const int base = (wm * 64 + i * 16 + r) * 36 + k0 + cq;
                a[i][0] = Au[base];
                a[i][1] = Au[base + 8 * 36];
                a[i][2] = Au[base + 4];
                a[i][3] = Au[base + 8 * 36 + 4];
            }
            #pragma unroll
            for (int j = 0; j < 4; j++) {
                const int base = (wn * 32 + j * 8 + r) * 36 + k0 + cq;
                b[j][0] = Bu[base];
                b[j][1] = Bu[base + 4];
            }
            #pragma unroll
            for (int i = 0; i < 4; i++)
                #pragma unroll
                for (int j = 0; j < 4; j++)
                    mma_tf32(acc[i][j], a[i], b[j]);
        }
        __syncthreads();
    }

    #pragma unroll
    for (int j = 0; j < 4; j++) {
        const int n = n0 + wn * 32 + j * 8 + cq * 2;
        const float b0 = __ldg(bih + n)     + __ldg(bhh + n);
        const float b1 = __ldg(bih + n + 1) + __ldg(bhh + n + 1);
        #pragma unroll
        for (int i = 0; i < 4; i++) {
            const int m = m0 + wm * 64 + i * 16 + r;
            float2 lo = { acc[i][j][0] + b0, acc[i][j][1] + b1 };
            float2 hi = { acc[i][j][2] + b0, acc[i][j][3] + b1 };
            *(float2*)(C + (size_t)m * G4 + n)       = lo;
            *(float2*)(C + (size_t)(m + 8) * G4 + n) = hi;
        }
    }
}

// ---------------------------------------------------------------------------
// prep: rna-round h0 -> g_hr[0] and reset grid barrier.
// ---------------------------------------------------------------------------
__global__ __launch_bounds__(256)
void prep(const float* __restrict__ h0)
{
    const int i4 = blockIdx.x * 256 + threadIdx.x;   // 0..16383
    float4 v = ((const float4*)h0)[i4];
    uint4 o;
    o.x = rna_tf32(v.x); o.y = rna_tf32(v.y);
    o.z = rna_tf32(v.z); o.w = rna_tf32(v.w);
    *(uint4*)(g_hr[0] + (size_t)i4 * 4) = o;
    if (i4 == 0) g_bar = 0;
}

// ---------------------------------------------------------------------------
// Persistent recurrence: tensorized, split-K-across-warps, 4-stage deep
// cp.async pipeline over 16 chunks of 64 k (prefetch distance 3 hides the
// per-chunk L2 delivery+latency that bound R14/R15).
//
// SMEM floats: Ws 32x1028 = 32896 | Hs 4 x 64x68 = 17408 (Gpart aliases)
//              Gb 64x34 = 2176 | Cs 512  -> 52992 floats (211968 B)
// ---------------------------------------------------------------------------
#define WS_STRIDE 1028
#define HS_OFF 32896
#define HS_STG (64 * 68)          // 4352 floats per stage
#define GB_OFF (HS_OFF + 4 * HS_STG)
#define CS_OFF (GB_OFF + 64 * 34)
#define SMEM_FLOATS (CS_OFF + 512)

// stage chunk ch (64 k) of hr into stage buffer s
__device__ __forceinline__ void stage_h(uint32_t hsb, int s, const float* hr,
                                        int ch, int tid)
{
    const uint32_t db = hsb + (uint32_t)(s * HS_STG) * 4;
    const float* src = hr + ch * 64;
    #pragma unroll
    for (int r8 = 0; r8 < 4; r8++) {
        const int id = tid + r8 * 256;     // 1024 float4s
        const int b = id >> 4, q = id & 15;
        cp16(db + (uint32_t)(b * 68 + q * 4) * 4,
             src + (size_t)b * HH + q * 4);
    }
    asm volatile("cp.async.commit_group;");
}

// mma for chunk ch out of stage buffer
__device__ __forceinline__ void mma_chunk(const float* sm, int ch,
                                          float acc[4][4][4],
                                          int kw8, int r, int cq)
{
    const uint32_t* Hu = (const uint32_t*)(sm + HS_OFF + (ch & 3) * HS_STG);
    const uint32_t* Wu = (const uint32_t*)sm;
    const int kg = ch * 64 + kw8;
    uint32_t b_[4][2];
    #pragma unroll
    for (int nt = 0; nt < 4; nt++) {
        const int bbase = (nt * 8 + r) * WS_STRIDE + kg + cq;
        b_[nt][0] = Wu[bbase];
        b_[nt][1] = Wu[bbase + 4];
    }
    #pragma unroll
    for (int mt = 0; mt < 4; mt++) {
        uint32_t a[4];
        const int abase = (mt * 16 + r) * 68 + kw8 + cq;
        a[0] = Hu[abase];
        a[1] = Hu[abase + 8 * 68];
        a[2] = Hu[abase + 4];
        a[3] = Hu[abase + 8 * 68 + 4];
        #pragma unroll
        for (int nt = 0; nt < 4; nt++)
            mma_tf32(acc[mt][nt], a, b_[nt]);
    }
}

__global__ __launch_bounds__(256, 1)
void lstm_persist(const float* __restrict__ xg, const float* c0,
                  const float* __restrict__ Whh,
                  float* out, float* hf, float* cf)
{
    extern __shared__ float sm[];
    float* Ws = sm;
    float* Gpart = sm + HS_OFF;            // aliases Hs after K-loop
    float* Gb = sm + GB_OFF;
    float* Cs = sm + CS_OFF;
    const uint32_t hsb = (uint32_t)__cvta_generic_to_shared(sm) + HS_OFF * 4;

    const int tid = threadIdx.x;
    const int nb  = blockIdx.x;            // 0..127

    // ---- load W slice (32 gate rows x 1024), rna-rounded -> Ws[col][k] ----
    {
        const int col = tid >> 3;
        const int l8  = tid & 7;
        const int grow = (col >> 3) * HH + nb * 8 + (col & 7);
        const float* wr = Whh + (size_t)grow * HH;
        for (int k0 = l8 * 4; k0 < II; k0 += 32) {
            float4 v = *(const float4*)(wr + k0);
            uint4 o;
            o.x = rna_tf32(v.x); o.y = rna_tf32(v.y);
            o.z = rna_tf32(v.z); o.w = rna_tf32(v.w);
            *(uint4*)(Ws + col * WS_STRIDE + k0) = o;
        }
    }
    #pragma unroll
    for (int r8 = 0; r8 < 2; r8++) {
        const int e = tid + r8 * 256;
        const int b = e >> 3, j = e & 7;
        Cs[e] = c0[(size_t)b * HH + nb * 8 + j];
    }
    __syncthreads();

    const int wid = tid >> 5, lid = tid & 31;
    const int r  = lid >> 2, cq = lid & 3;
    const int kw8 = wid * 8;               // warp's k-offset within 64-k chunk

    // ---- prefetch xg for step 0 ----
    float xvv[2][4];
    #pragma unroll
    for (int r8 = 0; r8 < 2; r8++) {
        const int e = tid + r8 * 256;
        const int b = e >> 3, j = e & 7;
        #pragma unroll
        for (int s = 0; s < 4; s++)
            xvv[r8][s] = __ldg(xg + (size_t)b * G4 + s * HH + nb * 8 + j);
    }

    for (int t = 0; t < TT; t++) {
        const float* hr_cur = g_hr[t & 1];
        float*       hr_nxt = g_hr[(t + 1) & 1];
        float*       out_t  = out + (size_t)t * BB * HH;

        // ---- prologue: stage chunks 0,1,2 ----
        stage_h(hsb, 0, hr_cur, 0, tid);
        stage_h(hsb, 1, hr_cur, 1, tid);
        stage_h(hsb, 2, hr_cur, 2, tid);

        float acc[4][4][4];
        #pragma unroll
        for (int i = 0; i < 4; i++)
            #pragma unroll
            for (int j = 0; j < 4; j++)
                #pragma unroll
                for (int q = 0; q < 4; q++) acc[i][j][q] = 0.0f;

        // ---- main loop: chunks 0..13, prefetch distance 3 ----
        for (int ch = 0; ch < 14; ch++) {
            asm volatile("cp.async.wait_group 2;");   // chunk ch arrived
            __syncthreads();   // visible to all; all warps past mma(ch-1)
            if (ch < 13)       // stage (ch+3)&3 last read at mma(ch-1)
                stage_h(hsb, (ch + 3) & 3, hr_cur, ch + 3, tid);
            mma_chunk(sm, ch, acc, kw8, r, cq);
        }
        // ---- tail: chunks 14,15 (both already arrived after drain) ----
        asm volatile("cp.async.wait_group 0;");
        __syncthreads();
        mma_chunk(sm, 14, acc, kw8, r, cq);
        mma_chunk(sm, 15, acc, kw8, r, cq);
        __syncthreads();       // all mma done before Gpart alias writes

        // ---- write per-warp partials to Gpart[w] (aliases Hs) ----
        {
            float* gp = Gpart + wid * 2112;
            #pragma unroll
            for (int mt = 0; mt < 4; mt++)
                #pragma unroll
                for (int nt = 0; nt < 4; nt++) {
                    const int row = mt * 16 + r;
                    const int col = nt * 8 + cq * 2;
                    gp[row * 33 + col]           = acc[mt][nt][0];
                    gp[row * 33 + col + 1]       = acc[mt][nt][1];
                    gp[(row + 8) * 33 + col]     = acc[mt][nt][2];
                    gp[(row + 8) * 33 + col + 1] = acc[mt][nt][3];
                }
        }
        __syncthreads();

        // ---- 8-way reduction -> Gb[b][col] ----
        {
            const int b = tid >> 2;
            const int colb = (tid & 3) * 8;
            #pragma unroll
            for (int j = 0; j < 8; j++) {
                const int off = b * 33 + colb + j;
                float s = Gpart[off];
                #pragma unroll
                for (int w = 1; w < 8; w++) s += Gpart[w * 2112 + off];
                Gb[b * 34 + colb + j] = s;
            }
        }
        __syncthreads();

        // ---- fused pointwise LSTM update ----
        #pragma unroll
        for (int r8 = 0; r8 < 2; r8++) {
            const int e = tid + r8 * 256;
            const int b = e >> 3, j = e & 7;
            const float ig = Gb[b * 34 + j]      + xvv[r8][0];
            const float fg = Gb[b * 34 + 8 + j]  + xvv[r8][1];
            const float gg = Gb[b * 34 + 16 + j] + xvv[r8][2];
            const float og = Gb[b * 34 + 24 + j] + xvv[r8][3];
            const float si = fsigm(ig);
            const float sf = fsigm(fg);
            const float so = fsigm(og);
            const float tg = ftanh(gg);
            const float cn = sf * Cs[e] + si * tg;
            const float hn = so * ftanh(cn);
            Cs[e] = cn;
            const int hc = nb * 8 + j;
            __stcg(out_t + (size_t)b * HH + hc, hn);
            __stcg(hr_nxt + (size_t)b * HH + hc, __uint_as_float(rna_tf32(hn)));
            if (t == TT - 1) {
                hf[(size_t)b * HH + hc] = hn;
                cf[(size_t)b * HH + hc] = cn;
            }
        }

        // ---- prefetch xg for step t+1 (hides under barrier) ----
        if (t + 1 < TT) {
            const float* xgn = xg + (size_t)(t + 1) * BB * G4;
            #pragma unroll
            for (int r8 = 0; r8 < 2; r8++) {
                const int e = tid + r8 * 256;
                const int b = e >> 3, j = e & 7;
                #pragma unroll
                for (int s = 0; s < 4; s++)
                    xvv[r8][s] = __ldg(xgn + (size_t)b * G4 + s * HH + nb * 8 + j);
            }
        }

        // ---- grid-wide barrier ----
        __syncthreads();
        if (tid == 0) {
            __threadfence();
            const unsigned target = (unsigned)(t + 1) * GRID;
            atomicAdd(&g_bar, 1u);
            while (*(volatile unsigned*)&g_bar < target) { }
            __threadfence();
        }
        __syncthreads();
    }
}

// ---------------------------------------------------------------------------
extern "C" void kernel_launch(void* const* d_in, const int* in_sizes, int n_in,
                              void* d_out, int out_size)
{
    const float* input = (const float*)d_in[0];
    const float* h0    = (const float*)d_in[1];
    const float* c0    = (const float*)d_in[2];
    const float* w_ih  = (const float*)d_in[3];
    const float* w_hh  = (const float*)d_in[4];
    const float* b_ih  = (const float*)d_in[5];
    const float* b_hh  = (const float*)d_in[6];

    float* outputs = (float*)d_out;                 // [T, B, H]
    float* hf = outputs + (size_t)TT * BB * HH;
    float* cf = hf + (size_t)BB * HH;

    float* xg = nullptr;
    cudaGetSymbolAddress((void**)&xg, g_xg);

    cudaFuncSetAttribute(gemm_mma,
                         cudaFuncAttributeMaxDynamicSharedMemorySize,
                         GEMM_SMEM);
    cudaFuncSetAttribute(lstm_persist,
                         cudaFuncAttributeMaxDynamicSharedMemorySize,
                         (int)(SMEM_FLOATS * sizeof(float)));

    cvt_tf32<<<T_F4 / 256, 256>>>(input, w_ih);
    gemm_mma<<<dim3(32, 256), 256, GEMM_SMEM>>>(b_ih, b_hh, xg);
    prep<<<64, 256>>>(h0);
    lstm_persist<<<GRID, 256, SMEM_FLOATS * sizeof(float)>>>(xg, c0, w_hh,
                                                             outputs, hf, cf);
}